// round 1
// baseline (speedup 1.0000x reference)
#include <cuda_runtime.h>
#include <cuda_bf16.h>
#include <math.h>

// ---------------------------------------------------------------------------
// Problem constants
// ---------------------------------------------------------------------------
#define TT 16          // frames
#define NQ 128         // queries
#define LATC 128       // feature channels
#define H0 96
#define W0 128
#define RR 7           // 2R+1
#define PP 49          // RR*RR
#define CV_DIM 2401    // 49*49
#define D_IN 1110
#define HID 384
#define EMB 256

// ---------------------------------------------------------------------------
// Static device scratch (no allocation allowed)
// ---------------------------------------------------------------------------
__device__ float g_pyr0[TT*96*128*LATC];
__device__ float g_pyr1[TT*48*64*LATC];
__device__ float g_pyr2[TT*24*32*LATC];
__device__ float g_pyr3[TT*12*16*LATC];
__device__ float g_tf  [4*NQ*PP*LATC];
__device__ float g_cv  [(size_t)4*TT*NQ*CV_DIM];
__device__ float g_h1  [(size_t)4*TT*NQ*HID];
__device__ float g_e   [(size_t)4*TT*NQ*EMB];
__device__ float g_x   [(size_t)NQ*TT*D_IN];
__device__ float g_h2  [(size_t)NQ*TT*HID];
__device__ float g_te  [TT*D_IN];
__device__ float g_coords[TT*NQ*2];
__device__ float g_vis [TT*NQ];
__device__ float g_conf[TT*NQ];

__device__ __forceinline__ float geluf(float x) {
    return 0.5f * x * (1.f + erff(x * 0.70710678118654752440f));
}

__device__ __forceinline__ const float* level_ptr(int l, int& Hl, int& Wl) {
    switch (l) {
        case 0: Hl = 96; Wl = 128; return g_pyr0;
        case 1: Hl = 48; Wl = 64;  return g_pyr1;
        case 2: Hl = 24; Wl = 32;  return g_pyr2;
        default:Hl = 12; Wl = 16;  return g_pyr3;
    }
}

// ---------------------------------------------------------------------------
// Time-embedding interpolation (50 -> 16)
// ---------------------------------------------------------------------------
__global__ void k_interp_te(const float* __restrict__ emb) {
    int i = blockIdx.x * blockDim.x + threadIdx.x;
    if (i >= TT * D_IN) return;
    int t = i / D_IN, d = i % D_IN;
    float j = ((float)t + 0.5f) * (50.f / 16.f) - 0.5f;
    j = fminf(fmaxf(j, 0.f), 49.f);
    int j0 = (int)floorf(j);
    int j1 = min(j0 + 1, 49);
    float w = j - (float)j0;
    g_te[i] = emb[j0 * D_IN + d] * (1.f - w) + emb[j1 * D_IN + d] * w;
}

// ---------------------------------------------------------------------------
// State init (must run every launch)
// ---------------------------------------------------------------------------
__global__ void k_init(const float* __restrict__ q) {
    int i = blockIdx.x * blockDim.x + threadIdx.x;
    if (i >= TT * NQ) return;
    int n = i % NQ;
    g_coords[i * 2 + 0] = q[n * 3 + 1] * 0.25f;
    g_coords[i * 2 + 1] = q[n * 3 + 2] * 0.25f;
    g_vis[i]  = 0.f;
    g_conf[i] = 0.f;
}

// ---------------------------------------------------------------------------
// 4x4/s4 conv + bias + channel L2 norm. 16 pixels per block, 128 threads (=ch)
// ---------------------------------------------------------------------------
__global__ __launch_bounds__(128) void k_conv(const float* __restrict__ video,
                                              const float* __restrict__ w,
                                              const float* __restrict__ b) {
    __shared__ float wsm[48][LATC];
    __shared__ float patch[16][49];
    __shared__ float wsum[4];
    int tid = threadIdx.x;
    for (int i = tid; i < 48 * LATC; i += 128) {
        int c = i / 48, k = i % 48;
        wsm[k][c] = w[i];
    }
    int base = blockIdx.x * 16;
    for (int i = tid; i < 16 * 48; i += 128) {
        int p = i / 48, k = i % 48;
        int idx = base + p;
        int x = idx & 127; int r = idx >> 7; int y = r % 96; int tf = r / 96;
        int ci = k / 16, kk = k % 16, ky = kk / 4, kx = kk % 4;
        float v = video[(((size_t)tf * 3 + ci) * 384 + (y * 4 + ky)) * 512 + (x * 4 + kx)];
        patch[p][k] = 2.f * (v * (1.f / 255.f)) - 1.f;
    }
    __syncthreads();
    float bia = b[tid];
    int lane = tid & 31, warp = tid >> 5;
    for (int p = 0; p < 16; p++) {
        float acc = bia;
#pragma unroll
        for (int k = 0; k < 48; k++) acc = fmaf(patch[p][k], wsm[k][tid], acc);
        float s = acc * acc;
#pragma unroll
        for (int o = 16; o; o >>= 1) s += __shfl_xor_sync(0xffffffffu, s, o);
        if (lane == 0) wsum[warp] = s;
        __syncthreads();
        float ss = wsum[0] + wsum[1] + wsum[2] + wsum[3];
        int idx = base + p;
        int x = idx & 127; int r = idx >> 7; int y = r % 96; int tf = r / 96;
        g_pyr0[(((size_t)tf * 96 + y) * 128 + x) * LATC + tid] = acc * rsqrtf(fmaxf(ss, 1e-12f));
        __syncthreads();
    }
}

// ---------------------------------------------------------------------------
// 2x2 avg pool, channel-last
// ---------------------------------------------------------------------------
__global__ void k_pool(int l) {
    const float* in; float* out; int Hi, Wi;
    if (l == 1)      { in = g_pyr0; out = g_pyr1; Hi = 96; Wi = 128; }
    else if (l == 2) { in = g_pyr1; out = g_pyr2; Hi = 48; Wi = 64; }
    else             { in = g_pyr2; out = g_pyr3; Hi = 24; Wi = 32; }
    int Ho = Hi / 2, Wo = Wi / 2;
    int total = TT * Ho * Wo * LATC;
    int i = blockIdx.x * blockDim.x + threadIdx.x;
    if (i >= total) return;
    int c = i & 127; int r = i >> 7;
    int x = r % Wo; r /= Wo;
    int y = r % Ho; int tf = r / Ho;
    const float* p = in + (((size_t)tf * Hi + 2 * y) * Wi + 2 * x) * LATC + c;
    size_t rs = (size_t)Wi * LATC;
    out[i] = 0.25f * (p[0] + p[LATC] + p[rs] + p[rs + LATC]);
}

// ---------------------------------------------------------------------------
// Template features: grid (n=128, l=4), 128 threads = channels
// ---------------------------------------------------------------------------
__global__ __launch_bounds__(128) void k_template(const float* __restrict__ q) {
    int n = blockIdx.x, l = blockIdx.y, c = threadIdx.x;
    int Hl, Wl;
    const float* fm = level_ptr(l, Hl, Wl);
    float qf = q[n * 3 + 0];
    float inv = exp2f(-(float)l) * 0.25f;
    float cx = q[n * 3 + 1] * inv, cy = q[n * 3 + 2] * inv;
    float tpos = fminf(fmaxf(qf, 0.f), (float)(TT - 1));
    int t0 = (int)floorf(tpos);
    float wt = tpos - (float)t0;
    int t1 = min(t0 + 1, TT - 1);
    const float* f0 = fm + (size_t)t0 * Hl * Wl * LATC;
    const float* f1 = fm + (size_t)t1 * Hl * Wl * LATC;
    float* dst = g_tf + (((size_t)l * NQ + n) * PP) * LATC + c;
    for (int p = 0; p < PP; p++) {
        int h = p / RR, ww = p % RR;
        float px = fminf(fmaxf(cx + (float)(h - 3), 0.f), (float)Wl - 1.f);
        float py = fminf(fmaxf(cy + (float)(ww - 3), 0.f), (float)Hl - 1.f);
        int x0 = (int)floorf(px); float wx = px - (float)x0; int x1 = min(x0 + 1, Wl - 1);
        int y0 = (int)floorf(py); float wy = py - (float)y0; int y1 = min(y0 + 1, Hl - 1);
        int o00 = (y0 * Wl + x0) * LATC + c, o01 = (y0 * Wl + x1) * LATC + c;
        int o10 = (y1 * Wl + x0) * LATC + c, o11 = (y1 * Wl + x1) * LATC + c;
        float v = (1.f - wy) * ((1.f - wx) * f0[o00] + wx * f0[o01])
                +        wy  * ((1.f - wx) * f0[o10] + wx * f0[o11]);
        if (wt > 0.f) {
            float v1 = (1.f - wy) * ((1.f - wx) * f1[o00] + wx * f1[o01])
                     +        wy  * ((1.f - wx) * f1[o10] + wx * f1[o11]);
            v = v * (1.f - wt) + v1 * wt;
        }
        dst[p * LATC] = v;
    }
}

// ---------------------------------------------------------------------------
// Fused bilinear sample + 49x49x128 correlation. grid (n,t,l), 192 threads.
// Dynamic smem: cf[49*132] + tf[49*132]
// ---------------------------------------------------------------------------
#define CORR_STRIDE 132
#define CORR_SMEM (2 * PP * CORR_STRIDE * (int)sizeof(float))

__global__ __launch_bounds__(192) void k_corr() {
    extern __shared__ float sh[];
    float* cfS = sh;
    float* tfS = sh + PP * CORR_STRIDE;
    __shared__ int   sO[PP][4];
    __shared__ float sW[PP][2];
    int n = blockIdx.x, t = blockIdx.y, l = blockIdx.z;
    int tid = threadIdx.x;
    int Hl, Wl;
    const float* fm = level_ptr(l, Hl, Wl);
    fm += (size_t)t * Hl * Wl * LATC;

    if (tid < PP) {
        float inv = exp2f(-(float)l);
        float cx = g_coords[(t * NQ + n) * 2 + 0] * inv;
        float cy = g_coords[(t * NQ + n) * 2 + 1] * inv;
        int h = tid / RR, ww = tid % RR;
        float px = fminf(fmaxf(cx + (float)(h - 3), 0.f), (float)Wl - 1.f);
        float py = fminf(fmaxf(cy + (float)(ww - 3), 0.f), (float)Hl - 1.f);
        int x0 = (int)floorf(px); float wx = px - (float)x0; int x1 = min(x0 + 1, Wl - 1);
        int y0 = (int)floorf(py); float wy = py - (float)y0; int y1 = min(y0 + 1, Hl - 1);
        sO[tid][0] = (y0 * Wl + x0) * LATC;
        sO[tid][1] = (y0 * Wl + x1) * LATC;
        sO[tid][2] = (y1 * Wl + x0) * LATC;
        sO[tid][3] = (y1 * Wl + x1) * LATC;
        sW[tid][0] = wx; sW[tid][1] = wy;
    }
    __syncthreads();

    const float* tfg = g_tf + (((size_t)l * NQ + n) * PP) * LATC;
    for (int i = tid; i < PP * LATC; i += 192) {
        int p = i >> 7, c = i & 127;
        float wx = sW[p][0], wy = sW[p][1];
        float v00 = fm[sO[p][0] + c], v01 = fm[sO[p][1] + c];
        float v10 = fm[sO[p][2] + c], v11 = fm[sO[p][3] + c];
        cfS[p * CORR_STRIDE + c] = (1.f - wy) * ((1.f - wx) * v00 + wx * v01)
                                 +        wy  * ((1.f - wx) * v10 + wx * v11);
        tfS[p * CORR_STRIDE + c] = tfg[i];
    }
    __syncthreads();

    if (tid < 169) {
        int tr = tid / 13, tc = tid % 13;
        const float* ca[4];
        const float* cb[4];
#pragma unroll
        for (int i = 0; i < 4; i++) {
            ca[i] = &cfS[min(tr * 4 + i, PP - 1) * CORR_STRIDE];
            cb[i] = &tfS[min(tc * 4 + i, PP - 1) * CORR_STRIDE];
        }
        float acc[4][4] = {};
        for (int k = 0; k < LATC; k += 4) {
            float4 a[4], bb[4];
#pragma unroll
            for (int i = 0; i < 4; i++) a[i]  = *(const float4*)(ca[i] + k);
#pragma unroll
            for (int j = 0; j < 4; j++) bb[j] = *(const float4*)(cb[j] + k);
#pragma unroll
            for (int i = 0; i < 4; i++)
#pragma unroll
                for (int j = 0; j < 4; j++) {
                    acc[i][j] = fmaf(a[i].x, bb[j].x, acc[i][j]);
                    acc[i][j] = fmaf(a[i].y, bb[j].y, acc[i][j]);
                    acc[i][j] = fmaf(a[i].z, bb[j].z, acc[i][j]);
                    acc[i][j] = fmaf(a[i].w, bb[j].w, acc[i][j]);
                }
        }
        float* cv = g_cv + ((size_t)((l * TT + t) * NQ + n)) * CV_DIM;
#pragma unroll
        for (int i = 0; i < 4; i++)
#pragma unroll
            for (int j = 0; j < 4; j++) {
                int hw = tr * 4 + i, ij = tc * 4 + j;
                if (hw < PP && ij < PP) cv[hw * PP + ij] = acc[i][j];
            }
    }
}

// ---------------------------------------------------------------------------
// Generic tiled fp32 GEMM: C(MxN) = act(A(MxK) @ B(KxN) + bias)
// BM=128, BN=64, BK=16, 256 threads, 8x4 microtile
// ---------------------------------------------------------------------------
__global__ __launch_bounds__(256) void k_gemm(const float* __restrict__ A,
                                              const float* __restrict__ B,
                                              const float* __restrict__ bias,
                                              float* __restrict__ C,
                                              int M, int N, int K, int act) {
    __shared__ float As[16][132];
    __shared__ float Bs[16][68];
    int tid = threadIdx.x;
    int tx = tid & 15, ty = tid >> 4;
    int row0 = blockIdx.y * 128, col0 = blockIdx.x * 64;
    float acc[8][4] = {};
    for (int k0 = 0; k0 < K; k0 += 16) {
#pragma unroll
        for (int r = 0; r < 8; r++) {
            int i = tid + r * 256;
            int m = i >> 4, kk = i & 15;
            int gm = row0 + m, gk = k0 + kk;
            As[kk][m] = (gm < M && gk < K) ? A[(size_t)gm * K + gk] : 0.f;
        }
#pragma unroll
        for (int r = 0; r < 4; r++) {
            int i = tid + r * 256;
            int kk = i >> 6, nn = i & 63;
            int gk = k0 + kk, gn = col0 + nn;
            Bs[kk][nn] = (gk < K && gn < N) ? B[(size_t)gk * N + gn] : 0.f;
        }
        __syncthreads();
#pragma unroll
        for (int kk = 0; kk < 16; kk++) {
            float4 a0 = *(const float4*)&As[kk][ty * 8];
            float4 a1 = *(const float4*)&As[kk][ty * 8 + 4];
            float4 b0 = *(const float4*)&Bs[kk][tx * 4];
            float a[8] = {a0.x, a0.y, a0.z, a0.w, a1.x, a1.y, a1.z, a1.w};
            float bb[4] = {b0.x, b0.y, b0.z, b0.w};
#pragma unroll
            for (int i2 = 0; i2 < 8; i2++)
#pragma unroll
                for (int j = 0; j < 4; j++) acc[i2][j] = fmaf(a[i2], bb[j], acc[i2][j]);
        }
        __syncthreads();
    }
#pragma unroll
    for (int i2 = 0; i2 < 8; i2++) {
        int gm = row0 + ty * 8 + i2;
        if (gm >= M) continue;
#pragma unroll
        for (int j = 0; j < 4; j++) {
            int gn = col0 + tx * 4 + j;
            if (gn >= N) continue;
            float v = acc[i2][j] + bias[gn];
            if (act) v = geluf(v);
            C[(size_t)gm * N + gn] = v;
        }
    }
}

// ---------------------------------------------------------------------------
// Assemble update-MLP input row (n*16+t): [vis, conf, corr(1024), posenc(84)] + te
// ---------------------------------------------------------------------------
__global__ __launch_bounds__(128) void k_assemble() {
    int row = blockIdx.x;          // n*TT + t
    int n = row >> 4, t = row & 15;
    int tid = threadIdx.x;
    __shared__ float x4[4];
    if (tid == 0) {
        float cx = g_coords[(t * NQ + n) * 2 + 0];
        float cy = g_coords[(t * NQ + n) * 2 + 1];
        float rfx = 0.f, rfy = 0.f, rbx = 0.f, rby = 0.f;
        if (t < TT - 1) {
            rfx = (cx - g_coords[((t + 1) * NQ + n) * 2 + 0]) * (1.f / 128.f);
            rfy = (cy - g_coords[((t + 1) * NQ + n) * 2 + 1]) * (1.f / 96.f);
        }
        if (t > 0) {
            rbx = (cx - g_coords[((t - 1) * NQ + n) * 2 + 0]) * (1.f / 128.f);
            rby = (cy - g_coords[((t - 1) * NQ + n) * 2 + 1]) * (1.f / 96.f);
        }
        x4[0] = rfx; x4[1] = rfy; x4[2] = rbx; x4[3] = rby;
    }
    __syncthreads();
    float* dst = g_x + (size_t)row * D_IN;
    for (int d = tid; d < D_IN; d += 128) {
        float v;
        if (d == 0) v = g_vis[t * NQ + n];
        else if (d == 1) v = g_conf[t * NQ + n];
        else if (d < 2 + 4 * EMB) {
            int qd = d - 2;
            int l = qd >> 8, k = qd & 255;
            v = g_e[(((size_t)(l * TT + t) * NQ + n) << 8) + k];
        } else {
            int j = d - (2 + 4 * EMB);
            if (j < 4) v = x4[j];
            else if (j < 44) {
                int s = (j - 4) >> 2, dd = (j - 4) & 3;
                v = sinf(x4[dd] * exp2f((float)s));
            } else {
                int s = (j - 44) >> 2, dd = (j - 44) & 3;
                v = cosf(x4[dd] * exp2f((float)s));
            }
        }
        dst[d] = v + g_te[t * D_IN + d];
    }
}

// ---------------------------------------------------------------------------
// Final tiny GEMV (384->4) + state update. one block per row (n*16+t)
// ---------------------------------------------------------------------------
__global__ __launch_bounds__(128) void k_update(const float* __restrict__ w2,
                                                const float* __restrict__ b2) {
    int row = blockIdx.x;
    int tid = threadIdx.x;
    const float* hrow = g_h2 + (size_t)row * HID;
    float a0 = 0.f, a1 = 0.f, a2 = 0.f, a3 = 0.f;
    for (int i = tid; i < HID; i += 128) {
        float h = hrow[i];
        const float* w = w2 + i * 4;
        a0 = fmaf(h, w[0], a0); a1 = fmaf(h, w[1], a1);
        a2 = fmaf(h, w[2], a2); a3 = fmaf(h, w[3], a3);
    }
#pragma unroll
    for (int o = 16; o; o >>= 1) {
        a0 += __shfl_xor_sync(0xffffffffu, a0, o);
        a1 += __shfl_xor_sync(0xffffffffu, a1, o);
        a2 += __shfl_xor_sync(0xffffffffu, a2, o);
        a3 += __shfl_xor_sync(0xffffffffu, a3, o);
    }
    __shared__ float red[4][4];
    int warp = tid >> 5, lane = tid & 31;
    if (lane == 0) { red[warp][0] = a0; red[warp][1] = a1; red[warp][2] = a2; red[warp][3] = a3; }
    __syncthreads();
    if (tid == 0) {
        float d0 = red[0][0] + red[1][0] + red[2][0] + red[3][0] + b2[0];
        float d1 = red[0][1] + red[1][1] + red[2][1] + red[3][1] + b2[1];
        float d2 = red[0][2] + red[1][2] + red[2][2] + red[3][2] + b2[2];
        float d3 = red[0][3] + red[1][3] + red[2][3] + red[3][3] + b2[3];
        int n = row >> 4, t = row & 15;
        g_coords[(t * NQ + n) * 2 + 0] += d0;
        g_coords[(t * NQ + n) * 2 + 1] += d1;
        g_vis[t * NQ + n]  += d2;
        g_conf[t * NQ + n] += d3;
    }
}

// ---------------------------------------------------------------------------
// Outputs: coords*4 (4096), sigmoid(vis) (2048), sigmoid(conf) (2048)
// ---------------------------------------------------------------------------
__global__ void k_output(float* __restrict__ out) {
    int i = blockIdx.x * blockDim.x + threadIdx.x;
    if (i >= 8192) return;
    if (i < 4096) out[i] = g_coords[i] * 4.f;
    else if (i < 6144) out[i] = 1.f / (1.f + expf(-g_vis[i - 4096]));
    else out[i] = 1.f / (1.f + expf(-g_conf[i - 6144]));
}

// ---------------------------------------------------------------------------
// Launch
// ---------------------------------------------------------------------------
extern "C" void kernel_launch(void* const* d_in, const int* in_sizes, int n_in,
                              void* d_out, int out_size) {
    const float* video   = (const float*)d_in[0];
    const float* queries = (const float*)d_in[1];
    const float* fnet_w  = (const float*)d_in[2];
    const float* fnet_b  = (const float*)d_in[3];
    const float* fc1_w   = (const float*)d_in[4];
    const float* fc1_b   = (const float*)d_in[5];
    const float* fc2_w   = (const float*)d_in[6];
    const float* fc2_b   = (const float*)d_in[7];
    const float* up_w1   = (const float*)d_in[8];
    const float* up_b1   = (const float*)d_in[9];
    const float* up_w2   = (const float*)d_in[10];
    const float* up_b2   = (const float*)d_in[11];
    const float* time_emb= (const float*)d_in[12];
    float* out = (float*)d_out;

    cudaFuncSetAttribute(k_corr, cudaFuncAttributeMaxDynamicSharedMemorySize, CORR_SMEM);

    float *p_cv, *p_h1, *p_e, *p_x, *p_h2;
    cudaGetSymbolAddress((void**)&p_cv, g_cv);
    cudaGetSymbolAddress((void**)&p_h1, g_h1);
    cudaGetSymbolAddress((void**)&p_e,  g_e);
    cudaGetSymbolAddress((void**)&p_x,  g_x);
    cudaGetSymbolAddress((void**)&p_h2, g_h2);

    // setup
    k_interp_te<<<(TT * D_IN + 255) / 256, 256>>>(time_emb);
    k_init<<<(TT * NQ + 127) / 128, 128>>>(queries);
    k_conv<<<TT * 96 * 128 / 16, 128>>>(video, fnet_w, fnet_b);
    k_pool<<<(TT * 48 * 64 * LATC + 255) / 256, 256>>>(1);
    k_pool<<<(TT * 24 * 32 * LATC + 255) / 256, 256>>>(2);
    k_pool<<<(TT * 12 * 16 * LATC + 255) / 256, 256>>>(3);
    k_template<<<dim3(NQ, 4), 128>>>(queries);

    const int M1 = 4 * TT * NQ;   // 8192
    const int M3 = NQ * TT;       // 2048
    for (int it = 0; it < 4; it++) {
        k_corr<<<dim3(NQ, TT, 4), 192, CORR_SMEM>>>();
        k_gemm<<<dim3((HID + 63) / 64, (M1 + 127) / 128), 256>>>(p_cv, fc1_w, fc1_b, p_h1, M1, HID, CV_DIM, 1);
        k_gemm<<<dim3((EMB + 63) / 64, (M1 + 127) / 128), 256>>>(p_h1, fc2_w, fc2_b, p_e, M1, EMB, HID, 0);
        k_assemble<<<M3, 128>>>();
        k_gemm<<<dim3((HID + 63) / 64, (M3 + 127) / 128), 256>>>(p_x, up_w1, up_b1, p_h2, M3, HID, D_IN, 1);
        k_update<<<M3, 128>>>(up_w2, up_b2);
    }
    k_output<<<(8192 + 255) / 256, 256>>>(out);
}

// round 2
// speedup vs baseline: 1.0010x; 1.0010x over previous
#include <cuda_runtime.h>
#include <cuda_bf16.h>
#include <math.h>

// ---------------------------------------------------------------------------
// Problem constants
// ---------------------------------------------------------------------------
#define TT 16          // frames
#define NQ 128         // queries
#define LATC 128       // feature channels
#define H0 96
#define W0 128
#define RR 7           // 2R+1
#define PP 49          // RR*RR
#define CV_DIM 2401    // 49*49
#define D_IN 1110
#define HID 384
#define EMB 256

// ---------------------------------------------------------------------------
// Static device scratch (no allocation allowed)
// ---------------------------------------------------------------------------
__device__ float g_pyr0[TT*96*128*LATC];
__device__ float g_pyr1[TT*48*64*LATC];
__device__ float g_pyr2[TT*24*32*LATC];
__device__ float g_pyr3[TT*12*16*LATC];
__device__ float g_tf  [4*NQ*PP*LATC];
__device__ float g_cv  [(size_t)4*TT*NQ*CV_DIM];
__device__ float g_h1  [(size_t)4*TT*NQ*HID];
__device__ float g_e   [(size_t)4*TT*NQ*EMB];
__device__ float g_x   [(size_t)NQ*TT*D_IN];
__device__ float g_h2  [(size_t)NQ*TT*HID];
__device__ float g_te  [TT*D_IN];
__device__ float g_coords[TT*NQ*2];
__device__ float g_vis [TT*NQ];
__device__ float g_conf[TT*NQ];

__device__ __forceinline__ float geluf(float x) {
    return 0.5f * x * (1.f + erff(x * 0.70710678118654752440f));
}

__device__ __forceinline__ const float* level_ptr(int l, int& Hl, int& Wl) {
    switch (l) {
        case 0: Hl = 96; Wl = 128; return g_pyr0;
        case 1: Hl = 48; Wl = 64;  return g_pyr1;
        case 2: Hl = 24; Wl = 32;  return g_pyr2;
        default:Hl = 12; Wl = 16;  return g_pyr3;
    }
}

// ---------------------------------------------------------------------------
// Time-embedding interpolation (50 -> 16)
// ---------------------------------------------------------------------------
__global__ void k_interp_te(const float* __restrict__ emb) {
    int i = blockIdx.x * blockDim.x + threadIdx.x;
    if (i >= TT * D_IN) return;
    int t = i / D_IN, d = i % D_IN;
    float j = ((float)t + 0.5f) * (50.f / 16.f) - 0.5f;
    j = fminf(fmaxf(j, 0.f), 49.f);
    int j0 = (int)floorf(j);
    int j1 = min(j0 + 1, 49);
    float w = j - (float)j0;
    g_te[i] = emb[j0 * D_IN + d] * (1.f - w) + emb[j1 * D_IN + d] * w;
}

// ---------------------------------------------------------------------------
// State init (must run every launch)
// ---------------------------------------------------------------------------
__global__ void k_init(const float* __restrict__ q) {
    int i = blockIdx.x * blockDim.x + threadIdx.x;
    if (i >= TT * NQ) return;
    int n = i % NQ;
    g_coords[i * 2 + 0] = q[n * 3 + 1] * 0.25f;
    g_coords[i * 2 + 1] = q[n * 3 + 2] * 0.25f;
    g_vis[i]  = 0.f;
    g_conf[i] = 0.f;
}

// ---------------------------------------------------------------------------
// 4x4/s4 conv + bias + channel L2 norm. 16 pixels per block, 128 threads (=ch)
// ---------------------------------------------------------------------------
__global__ __launch_bounds__(128) void k_conv(const float* __restrict__ video,
                                              const float* __restrict__ w,
                                              const float* __restrict__ b) {
    __shared__ float wsm[48][LATC];
    __shared__ float patch[16][49];
    __shared__ float wsum[4];
    int tid = threadIdx.x;
    for (int i = tid; i < 48 * LATC; i += 128) {
        int c = i / 48, k = i % 48;
        wsm[k][c] = w[i];
    }
    int base = blockIdx.x * 16;
    for (int i = tid; i < 16 * 48; i += 128) {
        int p = i / 48, k = i % 48;
        int idx = base + p;
        int x = idx & 127; int r = idx >> 7; int y = r % 96; int tf = r / 96;
        int ci = k / 16, kk = k % 16, ky = kk / 4, kx = kk % 4;
        float v = video[(((size_t)tf * 3 + ci) * 384 + (y * 4 + ky)) * 512 + (x * 4 + kx)];
        patch[p][k] = 2.f * (v * (1.f / 255.f)) - 1.f;
    }
    __syncthreads();
    float bia = b[tid];
    int lane = tid & 31, warp = tid >> 5;
    for (int p = 0; p < 16; p++) {
        float acc = bia;
#pragma unroll
        for (int k = 0; k < 48; k++) acc = fmaf(patch[p][k], wsm[k][tid], acc);
        float s = acc * acc;
#pragma unroll
        for (int o = 16; o; o >>= 1) s += __shfl_xor_sync(0xffffffffu, s, o);
        if (lane == 0) wsum[warp] = s;
        __syncthreads();
        float ss = wsum[0] + wsum[1] + wsum[2] + wsum[3];
        int idx = base + p;
        int x = idx & 127; int r = idx >> 7; int y = r % 96; int tf = r / 96;
        g_pyr0[(((size_t)tf * 96 + y) * 128 + x) * LATC + tid] = acc * rsqrtf(fmaxf(ss, 1e-12f));
        __syncthreads();
    }
}

// ---------------------------------------------------------------------------
// 2x2 avg pool, channel-last
// ---------------------------------------------------------------------------
__global__ void k_pool(int l) {
    const float* in; float* out; int Hi, Wi;
    if (l == 1)      { in = g_pyr0; out = g_pyr1; Hi = 96; Wi = 128; }
    else if (l == 2) { in = g_pyr1; out = g_pyr2; Hi = 48; Wi = 64; }
    else             { in = g_pyr2; out = g_pyr3; Hi = 24; Wi = 32; }
    int Ho = Hi / 2, Wo = Wi / 2;
    int total = TT * Ho * Wo * LATC;
    int i = blockIdx.x * blockDim.x + threadIdx.x;
    if (i >= total) return;
    int c = i & 127; int r = i >> 7;
    int x = r % Wo; r /= Wo;
    int y = r % Ho; int tf = r / Ho;
    const float* p = in + (((size_t)tf * Hi + 2 * y) * Wi + 2 * x) * LATC + c;
    size_t rs = (size_t)Wi * LATC;
    out[i] = 0.25f * (p[0] + p[LATC] + p[rs] + p[rs + LATC]);
}

// ---------------------------------------------------------------------------
// Template features: grid (n=128, l=4), 128 threads = channels
// ---------------------------------------------------------------------------
__global__ __launch_bounds__(128) void k_template(const float* __restrict__ q) {
    int n = blockIdx.x, l = blockIdx.y, c = threadIdx.x;
    int Hl, Wl;
    const float* fm = level_ptr(l, Hl, Wl);
    float qf = q[n * 3 + 0];
    float inv = exp2f(-(float)l) * 0.25f;
    float cx = q[n * 3 + 1] * inv, cy = q[n * 3 + 2] * inv;
    float tpos = fminf(fmaxf(qf, 0.f), (float)(TT - 1));
    int t0 = (int)floorf(tpos);
    float wt = tpos - (float)t0;
    int t1 = min(t0 + 1, TT - 1);
    const float* f0 = fm + (size_t)t0 * Hl * Wl * LATC;
    const float* f1 = fm + (size_t)t1 * Hl * Wl * LATC;
    float* dst = g_tf + (((size_t)l * NQ + n) * PP) * LATC + c;
    for (int p = 0; p < PP; p++) {
        int h = p / RR, ww = p % RR;
        float px = fminf(fmaxf(cx + (float)(h - 3), 0.f), (float)Wl - 1.f);
        float py = fminf(fmaxf(cy + (float)(ww - 3), 0.f), (float)Hl - 1.f);
        int x0 = (int)floorf(px); float wx = px - (float)x0; int x1 = min(x0 + 1, Wl - 1);
        int y0 = (int)floorf(py); float wy = py - (float)y0; int y1 = min(y0 + 1, Hl - 1);
        int o00 = (y0 * Wl + x0) * LATC + c, o01 = (y0 * Wl + x1) * LATC + c;
        int o10 = (y1 * Wl + x0) * LATC + c, o11 = (y1 * Wl + x1) * LATC + c;
        float v = (1.f - wy) * ((1.f - wx) * f0[o00] + wx * f0[o01])
                +        wy  * ((1.f - wx) * f0[o10] + wx * f0[o11]);
        if (wt > 0.f) {
            float v1 = (1.f - wy) * ((1.f - wx) * f1[o00] + wx * f1[o01])
                     +        wy  * ((1.f - wx) * f1[o10] + wx * f1[o11]);
            v = v * (1.f - wt) + v1 * wt;
        }
        dst[p * LATC] = v;
    }
}

// ---------------------------------------------------------------------------
// Fused bilinear sample + 49x49x128 correlation. grid (n,t,l), 192 threads.
// Dynamic smem: cf[49*132] + tf[49*132]
// ---------------------------------------------------------------------------
#define CORR_STRIDE 132
#define CORR_SMEM (2 * PP * CORR_STRIDE * (int)sizeof(float))

__global__ __launch_bounds__(192) void k_corr() {
    extern __shared__ float sh[];
    float* cfS = sh;
    float* tfS = sh + PP * CORR_STRIDE;
    __shared__ int   sO[PP][4];
    __shared__ float sW[PP][2];
    int n = blockIdx.x, t = blockIdx.y, l = blockIdx.z;
    int tid = threadIdx.x;
    int Hl, Wl;
    const float* fm = level_ptr(l, Hl, Wl);
    fm += (size_t)t * Hl * Wl * LATC;

    if (tid < PP) {
        float inv = exp2f(-(float)l);
        float cx = g_coords[(t * NQ + n) * 2 + 0] * inv;
        float cy = g_coords[(t * NQ + n) * 2 + 1] * inv;
        int h = tid / RR, ww = tid % RR;
        float px = fminf(fmaxf(cx + (float)(h - 3), 0.f), (float)Wl - 1.f);
        float py = fminf(fmaxf(cy + (float)(ww - 3), 0.f), (float)Hl - 1.f);
        int x0 = (int)floorf(px); float wx = px - (float)x0; int x1 = min(x0 + 1, Wl - 1);
        int y0 = (int)floorf(py); float wy = py - (float)y0; int y1 = min(y0 + 1, Hl - 1);
        sO[tid][0] = (y0 * Wl + x0) * LATC;
        sO[tid][1] = (y0 * Wl + x1) * LATC;
        sO[tid][2] = (y1 * Wl + x0) * LATC;
        sO[tid][3] = (y1 * Wl + x1) * LATC;
        sW[tid][0] = wx; sW[tid][1] = wy;
    }
    __syncthreads();

    const float* tfg = g_tf + (((size_t)l * NQ + n) * PP) * LATC;
    for (int i = tid; i < PP * LATC; i += 192) {
        int p = i >> 7, c = i & 127;
        float wx = sW[p][0], wy = sW[p][1];
        float v00 = fm[sO[p][0] + c], v01 = fm[sO[p][1] + c];
        float v10 = fm[sO[p][2] + c], v11 = fm[sO[p][3] + c];
        cfS[p * CORR_STRIDE + c] = (1.f - wy) * ((1.f - wx) * v00 + wx * v01)
                                 +        wy  * ((1.f - wx) * v10 + wx * v11);
        tfS[p * CORR_STRIDE + c] = tfg[i];
    }
    __syncthreads();

    if (tid < 169) {
        int tr = tid / 13, tc = tid % 13;
        const float* ca[4];
        const float* cb[4];
#pragma unroll
        for (int i = 0; i < 4; i++) {
            ca[i] = &cfS[min(tr * 4 + i, PP - 1) * CORR_STRIDE];
            cb[i] = &tfS[min(tc * 4 + i, PP - 1) * CORR_STRIDE];
        }
        float acc[4][4] = {};
        for (int k = 0; k < LATC; k += 4) {
            float4 a[4], bb[4];
#pragma unroll
            for (int i = 0; i < 4; i++) a[i]  = *(const float4*)(ca[i] + k);
#pragma unroll
            for (int j = 0; j < 4; j++) bb[j] = *(const float4*)(cb[j] + k);
#pragma unroll
            for (int i = 0; i < 4; i++)
#pragma unroll
                for (int j = 0; j < 4; j++) {
                    acc[i][j] = fmaf(a[i].x, bb[j].x, acc[i][j]);
                    acc[i][j] = fmaf(a[i].y, bb[j].y, acc[i][j]);
                    acc[i][j] = fmaf(a[i].z, bb[j].z, acc[i][j]);
                    acc[i][j] = fmaf(a[i].w, bb[j].w, acc[i][j]);
                }
        }
        float* cv = g_cv + ((size_t)((l * TT + t) * NQ + n)) * CV_DIM;
#pragma unroll
        for (int i = 0; i < 4; i++)
#pragma unroll
            for (int j = 0; j < 4; j++) {
                int hw = tr * 4 + i, ij = tc * 4 + j;
                if (hw < PP && ij < PP) cv[hw * PP + ij] = acc[i][j];
            }
    }
}

// ---------------------------------------------------------------------------
// Generic tiled fp32 GEMM: C(MxN) = act(A(MxK) @ B(KxN) + bias)
// BM=128, BN=64, BK=16, 256 threads, 8x4 microtile
// ---------------------------------------------------------------------------
__global__ __launch_bounds__(256) void k_gemm(const float* __restrict__ A,
                                              const float* __restrict__ B,
                                              const float* __restrict__ bias,
                                              float* __restrict__ C,
                                              int M, int N, int K, int act) {
    __shared__ float As[16][132];
    __shared__ float Bs[16][68];
    int tid = threadIdx.x;
    int tx = tid & 15, ty = tid >> 4;
    int row0 = blockIdx.y * 128, col0 = blockIdx.x * 64;
    float acc[8][4] = {};
    for (int k0 = 0; k0 < K; k0 += 16) {
#pragma unroll
        for (int r = 0; r < 8; r++) {
            int i = tid + r * 256;
            int m = i >> 4, kk = i & 15;
            int gm = row0 + m, gk = k0 + kk;
            As[kk][m] = (gm < M && gk < K) ? A[(size_t)gm * K + gk] : 0.f;
        }
#pragma unroll
        for (int r = 0; r < 4; r++) {
            int i = tid + r * 256;
            int kk = i >> 6, nn = i & 63;
            int gk = k0 + kk, gn = col0 + nn;
            Bs[kk][nn] = (gk < K && gn < N) ? B[(size_t)gk * N + gn] : 0.f;
        }
        __syncthreads();
#pragma unroll
        for (int kk = 0; kk < 16; kk++) {
            float4 a0 = *(const float4*)&As[kk][ty * 8];
            float4 a1 = *(const float4*)&As[kk][ty * 8 + 4];
            float4 b0 = *(const float4*)&Bs[kk][tx * 4];
            float a[8] = {a0.x, a0.y, a0.z, a0.w, a1.x, a1.y, a1.z, a1.w};
            float bb[4] = {b0.x, b0.y, b0.z, b0.w};
#pragma unroll
            for (int i2 = 0; i2 < 8; i2++)
#pragma unroll
                for (int j = 0; j < 4; j++) acc[i2][j] = fmaf(a[i2], bb[j], acc[i2][j]);
        }
        __syncthreads();
    }
#pragma unroll
    for (int i2 = 0; i2 < 8; i2++) {
        int gm = row0 + ty * 8 + i2;
        if (gm >= M) continue;
#pragma unroll
        for (int j = 0; j < 4; j++) {
            int gn = col0 + tx * 4 + j;
            if (gn >= N) continue;
            float v = acc[i2][j] + bias[gn];
            if (act) v = geluf(v);
            C[(size_t)gm * N + gn] = v;
        }
    }
}

// ---------------------------------------------------------------------------
// Assemble update-MLP input row (n*16+t): [vis, conf, corr(1024), posenc(84)] + te
// ---------------------------------------------------------------------------
__global__ __launch_bounds__(128) void k_assemble() {
    int row = blockIdx.x;          // n*TT + t
    int n = row >> 4, t = row & 15;
    int tid = threadIdx.x;
    __shared__ float x4[4];
    if (tid == 0) {
        float cx = g_coords[(t * NQ + n) * 2 + 0];
        float cy = g_coords[(t * NQ + n) * 2 + 1];
        float rfx = 0.f, rfy = 0.f, rbx = 0.f, rby = 0.f;
        if (t < TT - 1) {
            rfx = (cx - g_coords[((t + 1) * NQ + n) * 2 + 0]) * (1.f / 128.f);
            rfy = (cy - g_coords[((t + 1) * NQ + n) * 2 + 1]) * (1.f / 96.f);
        }
        if (t > 0) {
            rbx = (cx - g_coords[((t - 1) * NQ + n) * 2 + 0]) * (1.f / 128.f);
            rby = (cy - g_coords[((t - 1) * NQ + n) * 2 + 1]) * (1.f / 96.f);
        }
        x4[0] = rfx; x4[1] = rfy; x4[2] = rbx; x4[3] = rby;
    }
    __syncthreads();
    float* dst = g_x + (size_t)row * D_IN;
    for (int d = tid; d < D_IN; d += 128) {
        float v;
        if (d == 0) v = g_vis[t * NQ + n];
        else if (d == 1) v = g_conf[t * NQ + n];
        else if (d < 2 + 4 * EMB) {
            int qd = d - 2;
            int l = qd >> 8, k = qd & 255;
            v = g_e[(((size_t)(l * TT + t) * NQ + n) << 8) + k];
        } else {
            int j = d - (2 + 4 * EMB);
            if (j < 4) v = x4[j];
            else if (j < 44) {
                int s = (j - 4) >> 2, dd = (j - 4) & 3;
                v = sinf(x4[dd] * exp2f((float)s));
            } else {
                int s = (j - 44) >> 2, dd = (j - 44) & 3;
                v = cosf(x4[dd] * exp2f((float)s));
            }
        }
        dst[d] = v + g_te[t * D_IN + d];
    }
}

// ---------------------------------------------------------------------------
// Final tiny GEMV (384->4) + state update. one block per row (n*16+t)
// ---------------------------------------------------------------------------
__global__ __launch_bounds__(128) void k_update(const float* __restrict__ w2,
                                                const float* __restrict__ b2) {
    int row = blockIdx.x;
    int tid = threadIdx.x;
    const float* hrow = g_h2 + (size_t)row * HID;
    float a0 = 0.f, a1 = 0.f, a2 = 0.f, a3 = 0.f;
    for (int i = tid; i < HID; i += 128) {
        float h = hrow[i];
        const float* w = w2 + i * 4;
        a0 = fmaf(h, w[0], a0); a1 = fmaf(h, w[1], a1);
        a2 = fmaf(h, w[2], a2); a3 = fmaf(h, w[3], a3);
    }
#pragma unroll
    for (int o = 16; o; o >>= 1) {
        a0 += __shfl_xor_sync(0xffffffffu, a0, o);
        a1 += __shfl_xor_sync(0xffffffffu, a1, o);
        a2 += __shfl_xor_sync(0xffffffffu, a2, o);
        a3 += __shfl_xor_sync(0xffffffffu, a3, o);
    }
    __shared__ float red[4][4];
    int warp = tid >> 5, lane = tid & 31;
    if (lane == 0) { red[warp][0] = a0; red[warp][1] = a1; red[warp][2] = a2; red[warp][3] = a3; }
    __syncthreads();
    if (tid == 0) {
        float d0 = red[0][0] + red[1][0] + red[2][0] + red[3][0] + b2[0];
        float d1 = red[0][1] + red[1][1] + red[2][1] + red[3][1] + b2[1];
        float d2 = red[0][2] + red[1][2] + red[2][2] + red[3][2] + b2[2];
        float d3 = red[0][3] + red[1][3] + red[2][3] + red[3][3] + b2[3];
        int n = row >> 4, t = row & 15;
        g_coords[(t * NQ + n) * 2 + 0] += d0;
        g_coords[(t * NQ + n) * 2 + 1] += d1;
        g_vis[t * NQ + n]  += d2;
        g_conf[t * NQ + n] += d3;
    }
}

// ---------------------------------------------------------------------------
// Outputs: coords*4 (4096), sigmoid(vis) (2048), sigmoid(conf) (2048)
// ---------------------------------------------------------------------------
__global__ void k_output(float* __restrict__ out) {
    int i = blockIdx.x * blockDim.x + threadIdx.x;
    if (i >= 8192) return;
    if (i < 4096) out[i] = g_coords[i] * 4.f;
    else if (i < 6144) out[i] = 1.f / (1.f + expf(-g_vis[i - 4096]));
    else out[i] = 1.f / (1.f + expf(-g_conf[i - 6144]));
}

// ---------------------------------------------------------------------------
// Launch
// ---------------------------------------------------------------------------
extern "C" void kernel_launch(void* const* d_in, const int* in_sizes, int n_in,
                              void* d_out, int out_size) {
    const float* video   = (const float*)d_in[0];
    const float* queries = (const float*)d_in[1];
    const float* fnet_w  = (const float*)d_in[2];
    const float* fnet_b  = (const float*)d_in[3];
    const float* fc1_w   = (const float*)d_in[4];
    const float* fc1_b   = (const float*)d_in[5];
    const float* fc2_w   = (const float*)d_in[6];
    const float* fc2_b   = (const float*)d_in[7];
    const float* up_w1   = (const float*)d_in[8];
    const float* up_b1   = (const float*)d_in[9];
    const float* up_w2   = (const float*)d_in[10];
    const float* up_b2   = (const float*)d_in[11];
    const float* time_emb= (const float*)d_in[12];
    float* out = (float*)d_out;

    cudaFuncSetAttribute(k_corr, cudaFuncAttributeMaxDynamicSharedMemorySize, CORR_SMEM);

    float *p_cv, *p_h1, *p_e, *p_x, *p_h2;
    cudaGetSymbolAddress((void**)&p_cv, g_cv);
    cudaGetSymbolAddress((void**)&p_h1, g_h1);
    cudaGetSymbolAddress((void**)&p_e,  g_e);
    cudaGetSymbolAddress((void**)&p_x,  g_x);
    cudaGetSymbolAddress((void**)&p_h2, g_h2);

    // setup
    k_interp_te<<<(TT * D_IN + 255) / 256, 256>>>(time_emb);
    k_init<<<(TT * NQ + 127) / 128, 128>>>(queries);
    k_conv<<<TT * 96 * 128 / 16, 128>>>(video, fnet_w, fnet_b);
    k_pool<<<(TT * 48 * 64 * LATC + 255) / 256, 256>>>(1);
    k_pool<<<(TT * 24 * 32 * LATC + 255) / 256, 256>>>(2);
    k_pool<<<(TT * 12 * 16 * LATC + 255) / 256, 256>>>(3);
    k_template<<<dim3(NQ, 4), 128>>>(queries);

    const int M1 = 4 * TT * NQ;   // 8192
    const int M3 = NQ * TT;       // 2048
    for (int it = 0; it < 4; it++) {
        k_corr<<<dim3(NQ, TT, 4), 192, CORR_SMEM>>>();
        k_gemm<<<dim3((HID + 63) / 64, (M1 + 127) / 128), 256>>>(p_cv, fc1_w, fc1_b, p_h1, M1, HID, CV_DIM, 1);
        k_gemm<<<dim3((EMB + 63) / 64, (M1 + 127) / 128), 256>>>(p_h1, fc2_w, fc2_b, p_e, M1, EMB, HID, 0);
        k_assemble<<<M3, 128>>>();
        k_gemm<<<dim3((HID + 63) / 64, (M3 + 127) / 128), 256>>>(p_x, up_w1, up_b1, p_h2, M3, HID, D_IN, 1);
        k_update<<<M3, 128>>>(up_w2, up_b2);
    }
    k_output<<<(8192 + 255) / 256, 256>>>(out);
}

// round 4
// speedup vs baseline: 2.9677x; 2.9648x over previous
#include <cuda_runtime.h>
#include <cuda_bf16.h>
#include <math.h>
#include <stdint.h>

#define TT 16
#define NQ 128
#define LATC 128
#define RR 7
#define PP 49
#define CV_K 2432      // 2401 padded to mult of 32
#define X_K 1152       // 1110 padded
#define HID 384
#define EMB 256
#define D_IN 1110

// ---------------------------------------------------------------------------
// Static device scratch
// ---------------------------------------------------------------------------
__device__ float g_pyr0[TT*96*128*LATC];
__device__ float g_pyr1[TT*48*64*LATC];
__device__ float g_pyr2[TT*24*32*LATC];
__device__ float g_pyr3[TT*12*16*LATC];
__device__ __nv_bfloat16 g_tf[(size_t)4*NQ*PP*LATC];
__device__ __nv_bfloat16 g_cv[(size_t)4*TT*NQ*CV_K];
__device__ __nv_bfloat16 g_h1[(size_t)4*TT*NQ*HID];
__device__ float         g_e [(size_t)4*TT*NQ*EMB];
__device__ __nv_bfloat16 g_x [(size_t)NQ*TT*X_K];
__device__ float         g_h2[(size_t)NQ*TT*HID];
__device__ __nv_bfloat16 g_w1t[(size_t)HID*CV_K];
__device__ __nv_bfloat16 g_w2t[(size_t)EMB*HID];
__device__ __nv_bfloat16 g_u1t[(size_t)HID*X_K];
__device__ float g_te[TT*D_IN];
__device__ float g_coords[TT*NQ*2];
__device__ float g_vis [TT*NQ];
__device__ float g_conf[TT*NQ];

__device__ __forceinline__ float geluf(float x) {
    return 0.5f * x * (1.f + erff(x * 0.70710678118654752440f));
}

__device__ __forceinline__ const float* level_ptr(int l, int& Hl, int& Wl) {
    switch (l) {
        case 0: Hl = 96; Wl = 128; return g_pyr0;
        case 1: Hl = 48; Wl = 64;  return g_pyr1;
        case 2: Hl = 24; Wl = 32;  return g_pyr2;
        default:Hl = 12; Wl = 16;  return g_pyr3;
    }
}

// ---------------------------------------------------------------------------
// mma.sync / ldmatrix helpers (baseline PTX, safe on sm_103 non-'a' target)
// ---------------------------------------------------------------------------
__device__ __forceinline__ uint32_t smem_u32(const void* p) {
    uint32_t a;
    asm("{ .reg .u64 t; cvta.to.shared.u64 t, %1; cvt.u32.u64 %0, t; }" : "=r"(a) : "l"(p));
    return a;
}
__device__ __forceinline__ void ldsm4(uint32_t* r, uint32_t a) {
    asm volatile("ldmatrix.sync.aligned.m8n8.x4.shared.b16 {%0,%1,%2,%3}, [%4];"
        : "=r"(r[0]), "=r"(r[1]), "=r"(r[2]), "=r"(r[3]) : "r"(a));
}
__device__ __forceinline__ void mma_bf16(float* d, const uint32_t* a, const uint32_t* b) {
    asm volatile("mma.sync.aligned.m16n8k16.row.col.f32.bf16.bf16.f32 "
        "{%0,%1,%2,%3},{%4,%5,%6,%7},{%8,%9},{%0,%1,%2,%3};"
        : "+f"(d[0]), "+f"(d[1]), "+f"(d[2]), "+f"(d[3])
        : "r"(a[0]), "r"(a[1]), "r"(a[2]), "r"(a[3]), "r"(b[0]), "r"(b[1]));
}

// ---------------------------------------------------------------------------
// Time-embedding interpolation (50 -> 16)
// ---------------------------------------------------------------------------
__global__ void k_interp_te(const float* __restrict__ emb) {
    int i = blockIdx.x * blockDim.x + threadIdx.x;
    if (i >= TT * D_IN) return;
    int t = i / D_IN, d = i % D_IN;
    float j = ((float)t + 0.5f) * (50.f / 16.f) - 0.5f;
    j = fminf(fmaxf(j, 0.f), 49.f);
    int j0 = (int)floorf(j);
    int j1 = min(j0 + 1, 49);
    float w = j - (float)j0;
    g_te[i] = emb[j0 * D_IN + d] * (1.f - w) + emb[j1 * D_IN + d] * w;
}

// ---------------------------------------------------------------------------
// State init
// ---------------------------------------------------------------------------
__global__ void k_init(const float* __restrict__ q) {
    int i = blockIdx.x * blockDim.x + threadIdx.x;
    if (i >= TT * NQ) return;
    int n = i % NQ;
    g_coords[i * 2 + 0] = q[n * 3 + 1] * 0.25f;
    g_coords[i * 2 + 1] = q[n * 3 + 2] * 0.25f;
    g_vis[i]  = 0.f;
    g_conf[i] = 0.f;
}

// ---------------------------------------------------------------------------
// 4x4/s4 conv + bias + channel L2 norm
// ---------------------------------------------------------------------------
__global__ __launch_bounds__(128) void k_conv(const float* __restrict__ video,
                                              const float* __restrict__ w,
                                              const float* __restrict__ b) {
    __shared__ float wsm[48][LATC];
    __shared__ float patch[16][49];
    __shared__ float wsum[4];
    int tid = threadIdx.x;
    for (int i = tid; i < 48 * LATC; i += 128) {
        int c = i / 48, k = i % 48;
        wsm[k][c] = w[i];
    }
    int base = blockIdx.x * 16;
    for (int i = tid; i < 16 * 48; i += 128) {
        int p = i / 48, k = i % 48;
        int idx = base + p;
        int x = idx & 127; int r = idx >> 7; int y = r % 96; int tf = r / 96;
        int ci = k / 16, kk = k % 16, ky = kk / 4, kx = kk % 4;
        float v = video[(((size_t)tf * 3 + ci) * 384 + (y * 4 + ky)) * 512 + (x * 4 + kx)];
        patch[p][k] = 2.f * (v * (1.f / 255.f)) - 1.f;
    }
    __syncthreads();
    float bia = b[tid];
    int lane = tid & 31, warp = tid >> 5;
    for (int p = 0; p < 16; p++) {
        float acc = bia;
#pragma unroll
        for (int k = 0; k < 48; k++) acc = fmaf(patch[p][k], wsm[k][tid], acc);
        float s = acc * acc;
#pragma unroll
        for (int o = 16; o; o >>= 1) s += __shfl_xor_sync(0xffffffffu, s, o);
        if (lane == 0) wsum[warp] = s;
        __syncthreads();
        float ss = wsum[0] + wsum[1] + wsum[2] + wsum[3];
        int idx = base + p;
        int x = idx & 127; int r = idx >> 7; int y = r % 96; int tf = r / 96;
        g_pyr0[(((size_t)tf * 96 + y) * 128 + x) * LATC + tid] = acc * rsqrtf(fmaxf(ss, 1e-12f));
        __syncthreads();
    }
}

// ---------------------------------------------------------------------------
// 2x2 avg pool
// ---------------------------------------------------------------------------
__global__ void k_pool(int l) {
    const float* in; float* out; int Hi, Wi;
    if (l == 1)      { in = g_pyr0; out = g_pyr1; Hi = 96; Wi = 128; }
    else if (l == 2) { in = g_pyr1; out = g_pyr2; Hi = 48; Wi = 64; }
    else             { in = g_pyr2; out = g_pyr3; Hi = 24; Wi = 32; }
    int Ho = Hi / 2, Wo = Wi / 2;
    int total = TT * Ho * Wo * LATC;
    int i = blockIdx.x * blockDim.x + threadIdx.x;
    if (i >= total) return;
    int c = i & 127; int r = i >> 7;
    int x = r % Wo; r /= Wo;
    int y = r % Ho; int tf = r / Ho;
    const float* p = in + (((size_t)tf * Hi + 2 * y) * Wi + 2 * x) * LATC + c;
    size_t rs = (size_t)Wi * LATC;
    out[i] = 0.25f * (p[0] + p[LATC] + p[rs] + p[rs + LATC]);
}

// ---------------------------------------------------------------------------
// Template features -> bf16 [l][n][p][c]
// ---------------------------------------------------------------------------
__global__ __launch_bounds__(128) void k_template(const float* __restrict__ q) {
    int n = blockIdx.x, l = blockIdx.y, c = threadIdx.x;
    int Hl, Wl;
    const float* fm = level_ptr(l, Hl, Wl);
    float qf = q[n * 3 + 0];
    float inv = exp2f(-(float)l) * 0.25f;
    float cx = q[n * 3 + 1] * inv, cy = q[n * 3 + 2] * inv;
    float tpos = fminf(fmaxf(qf, 0.f), (float)(TT - 1));
    int t0 = (int)floorf(tpos);
    float wt = tpos - (float)t0;
    int t1 = min(t0 + 1, TT - 1);
    const float* f0 = fm + (size_t)t0 * Hl * Wl * LATC;
    const float* f1 = fm + (size_t)t1 * Hl * Wl * LATC;
    __nv_bfloat16* dst = g_tf + (((size_t)l * NQ + n) * PP) * LATC + c;
    for (int p = 0; p < PP; p++) {
        int h = p / RR, ww = p % RR;
        float px = fminf(fmaxf(cx + (float)(h - 3), 0.f), (float)Wl - 1.f);
        float py = fminf(fmaxf(cy + (float)(ww - 3), 0.f), (float)Hl - 1.f);
        int x0 = (int)floorf(px); float wx = px - (float)x0; int x1 = min(x0 + 1, Wl - 1);
        int y0 = (int)floorf(py); float wy = py - (float)y0; int y1 = min(y0 + 1, Hl - 1);
        int o00 = (y0 * Wl + x0) * LATC + c, o01 = (y0 * Wl + x1) * LATC + c;
        int o10 = (y1 * Wl + x0) * LATC + c, o11 = (y1 * Wl + x1) * LATC + c;
        float v = (1.f - wy) * ((1.f - wx) * f0[o00] + wx * f0[o01])
                +        wy  * ((1.f - wx) * f0[o10] + wx * f0[o11]);
        if (wt > 0.f) {
            float v1 = (1.f - wy) * ((1.f - wx) * f1[o00] + wx * f1[o01])
                     +        wy  * ((1.f - wx) * f1[o10] + wx * f1[o11]);
            v = v * (1.f - wt) + v1 * wt;
        }
        dst[p * LATC] = __float2bfloat16(v);
    }
}

// ---------------------------------------------------------------------------
// Weight transpose fp32[K][N] -> bf16[N][Kpad], zero pad
// ---------------------------------------------------------------------------
__global__ void k_wt(const float* __restrict__ w, __nv_bfloat16* __restrict__ wt,
                     int K, int N, int Kpad) {
    int i = blockIdx.x * blockDim.x + threadIdx.x;
    if (i >= N * Kpad) return;
    int n = i / Kpad, k = i - n * Kpad;
    wt[i] = __float2bfloat16((k < K) ? w[(size_t)k * N + n] : 0.f);
}

__global__ void k_padzero(__nv_bfloat16* buf, int rows, int stride, int c0, int cw) {
    int i = blockIdx.x * blockDim.x + threadIdx.x;
    if (i >= rows * cw) return;
    int r = i / cw, c = i - r * cw;
    buf[(size_t)r * stride + c0 + c] = __float2bfloat16(0.f);
}

// ---------------------------------------------------------------------------
// Fused bilinear sample + 49x49x128 correlation via mma.sync.
// Block = (n, t, l), 128 threads (4 warps). Each warp: all M (4 frags), 16 N.
// ---------------------------------------------------------------------------
#define CS 136

__global__ __launch_bounds__(128) void k_corr_mma() {
    __shared__ __nv_bfloat16 cf[64 * CS];
    __shared__ __nv_bfloat16 tf[64 * CS];
    __shared__ int   sO[PP][4];
    __shared__ float sW[PP][2];
    int n = blockIdx.x, t = blockIdx.y, l = blockIdx.z;
    int tid = threadIdx.x, lane = tid & 31, w = tid >> 5;
    int Hl, Wl;
    const float* fm = level_ptr(l, Hl, Wl);
    fm += (size_t)t * Hl * Wl * LATC;

    if (tid < PP) {
        float inv = exp2f(-(float)l);
        float cx = g_coords[(t * NQ + n) * 2 + 0] * inv;
        float cy = g_coords[(t * NQ + n) * 2 + 1] * inv;
        int h = tid / RR, ww = tid % RR;
        float px = fminf(fmaxf(cx + (float)(h - 3), 0.f), (float)Wl - 1.f);
        float py = fminf(fmaxf(cy + (float)(ww - 3), 0.f), (float)Hl - 1.f);
        int x0 = (int)floorf(px); float wx = px - (float)x0; int x1 = min(x0 + 1, Wl - 1);
        int y0 = (int)floorf(py); float wy = py - (float)y0; int y1 = min(y0 + 1, Hl - 1);
        sO[tid][0] = (y0 * Wl + x0) * LATC;
        sO[tid][1] = (y0 * Wl + x1) * LATC;
        sO[tid][2] = (y1 * Wl + x0) * LATC;
        sO[tid][3] = (y1 * Wl + x1) * LATC;
        sW[tid][0] = wx; sW[tid][1] = wy;
    }
    // zero pad rows 49..63 of both tiles
    for (int i = tid; i < 15 * CS; i += 128) {
        cf[49 * CS + i] = __float2bfloat16(0.f);
        tf[49 * CS + i] = __float2bfloat16(0.f);
    }
    // load template tile (49x128 bf16, 16B chunks)
    const __nv_bfloat16* tfg = g_tf + (((size_t)l * NQ + n) * PP) * LATC;
    for (int i = tid; i < PP * 16; i += 128) {
        int p = i >> 4, c8 = (i & 15) << 3;
        *(uint4*)&tf[p * CS + c8] = *(const uint4*)(tfg + p * LATC + c8);
    }
    __syncthreads();
    // bilinear sample cf (49x128)
    for (int i = tid; i < PP * LATC; i += 128) {
        int p = i >> 7, c = i & 127;
        float wx = sW[p][0], wy = sW[p][1];
        float v00 = fm[sO[p][0] + c], v01 = fm[sO[p][1] + c];
        float v10 = fm[sO[p][2] + c], v11 = fm[sO[p][3] + c];
        float v = (1.f - wy) * ((1.f - wx) * v00 + wx * v01)
                +        wy  * ((1.f - wx) * v10 + wx * v11);
        cf[p * CS + c] = __float2bfloat16(v);
    }
    __syncthreads();

    float acc[4][2][4] = {};
#pragma unroll
    for (int ks = 0; ks < 8; ks++) {
        uint32_t b[2][2];
        {
            uint32_t rr[4];
            uint32_t addr = smem_u32(&tf[((w << 4) + ((lane >> 4) << 3) + (lane & 7)) * CS
                                         + (ks << 4) + (((lane >> 3) & 1) << 3)]);
            ldsm4(rr, addr);
            b[0][0] = rr[0]; b[0][1] = rr[1]; b[1][0] = rr[2]; b[1][1] = rr[3];
        }
#pragma unroll
        for (int f = 0; f < 4; f++) {
            uint32_t a[4];
            ldsm4(a, smem_u32(&cf[((f << 4) + (lane & 15)) * CS + (ks << 4) + ((lane >> 4) << 3)]));
            mma_bf16(acc[f][0], a, b[0]);
            mma_bf16(acc[f][1], a, b[1]);
        }
    }

    __nv_bfloat16* cv = g_cv + ((size_t)((l * TT + t) * NQ + n)) * CV_K;
#pragma unroll
    for (int f = 0; f < 4; f++) {
        int m0 = (f << 4) + (lane >> 2);
#pragma unroll
        for (int g = 0; g < 2; g++) {
            int nn = (w << 4) + (g << 3) + ((lane & 3) << 1);
            if (nn < PP) {
                if (m0 < PP) cv[m0 * PP + nn] = __float2bfloat16(acc[f][g][0]);
                if (m0 + 8 < PP) cv[(m0 + 8) * PP + nn] = __float2bfloat16(acc[f][g][2]);
                if (nn + 1 < PP) {
                    if (m0 < PP) cv[m0 * PP + nn + 1] = __float2bfloat16(acc[f][g][1]);
                    if (m0 + 8 < PP) cv[(m0 + 8) * PP + nn + 1] = __float2bfloat16(acc[f][g][3]);
                }
            }
        }
    }
}

// ---------------------------------------------------------------------------
// bf16 mma.sync GEMM: C(MxN) = act(A @ Bt^T + bias). A:[M][K], Bt:[N][K] bf16.
// CTA tile 128x128, BK=32, 256 threads (8 warps = 2Mx4N), warp tile 64x32.
// M, N multiples of 128; K multiple of 32.
// ---------------------------------------------------------------------------
#define GST 40

__global__ __launch_bounds__(256) void k_gemm_bf(const __nv_bfloat16* __restrict__ A,
                                                 const __nv_bfloat16* __restrict__ Bt,
                                                 const float* __restrict__ bias,
                                                 void* __restrict__ Cv,
                                                 int M, int N, int K, int act, int outbf) {
    __shared__ __nv_bfloat16 As[2][128 * GST];
    __shared__ __nv_bfloat16 Bs[2][128 * GST];
    int tid = threadIdx.x, lane = tid & 31, warp = tid >> 5;
    int wm = (warp & 1) << 6, wn = (warp >> 1) << 5;
    int row0 = blockIdx.y << 7, col0 = blockIdx.x << 7;
    const __nv_bfloat16* Ag = A  + (size_t)row0 * K;
    const __nv_bfloat16* Bg = Bt + (size_t)col0 * K;

    float acc[4][4][4] = {};
#pragma unroll
    for (int c = 0; c < 2; c++) {
        int q = tid + (c << 8);
        int r = q >> 2, c8 = (q & 3) << 3;
        *(uint4*)(As[0] + r * GST + c8) = *(const uint4*)(Ag + (size_t)r * K + c8);
        *(uint4*)(Bs[0] + r * GST + c8) = *(const uint4*)(Bg + (size_t)r * K + c8);
    }
    __syncthreads();
    int nk = K >> 5;
    for (int i = 0; i < nk; i++) {
        int s = i & 1;
        if (i + 1 < nk) {
            int k0 = (i + 1) << 5, s2 = s ^ 1;
#pragma unroll
            for (int c = 0; c < 2; c++) {
                int q = tid + (c << 8);
                int r = q >> 2, c8 = (q & 3) << 3;
                *(uint4*)(As[s2] + r * GST + c8) = *(const uint4*)(Ag + (size_t)r * K + k0 + c8);
                *(uint4*)(Bs[s2] + r * GST + c8) = *(const uint4*)(Bg + (size_t)r * K + k0 + c8);
            }
        }
#pragma unroll
        for (int ks = 0; ks < 2; ks++) {
            uint32_t b[4][2];
#pragma unroll
            for (int g = 0; g < 2; g++) {
                uint32_t rr[4];
                uint32_t addr = smem_u32(Bs[s] + (wn + (g << 4) + ((lane >> 4) << 3) + (lane & 7)) * GST
                                         + (ks << 4) + (((lane >> 3) & 1) << 3));
                ldsm4(rr, addr);
                b[g * 2][0] = rr[0]; b[g * 2][1] = rr[1];
                b[g * 2 + 1][0] = rr[2]; b[g * 2 + 1][1] = rr[3];
            }
#pragma unroll
            for (int f = 0; f < 4; f++) {
                uint32_t a[4];
                ldsm4(a, smem_u32(As[s] + (wm + (f << 4) + (lane & 15)) * GST
                                  + (ks << 4) + ((lane >> 4) << 3)));
#pragma unroll
                for (int g = 0; g < 4; g++) mma_bf16(acc[f][g], a, b[g]);
            }
        }
        __syncthreads();
    }
#pragma unroll
    for (int f = 0; f < 4; f++) {
        int m = row0 + wm + (f << 4) + (lane >> 2);
#pragma unroll
        for (int g = 0; g < 4; g++) {
            int nn = col0 + wn + (g << 3) + ((lane & 3) << 1);
            float b0 = bias[nn], b1 = bias[nn + 1];
            float v0 = acc[f][g][0] + b0, v1 = acc[f][g][1] + b1;
            float v2 = acc[f][g][2] + b0, v3 = acc[f][g][3] + b1;
            if (act) { v0 = geluf(v0); v1 = geluf(v1); v2 = geluf(v2); v3 = geluf(v3); }
            if (outbf) {
                __nv_bfloat16* C = (__nv_bfloat16*)Cv;
                C[(size_t)m * N + nn] = __float2bfloat16(v0);
                C[(size_t)m * N + nn + 1] = __float2bfloat16(v1);
                C[(size_t)(m + 8) * N + nn] = __float2bfloat16(v2);
                C[(size_t)(m + 8) * N + nn + 1] = __float2bfloat16(v3);
            } else {
                float* C = (float*)Cv;
                C[(size_t)m * N + nn] = v0;
                C[(size_t)m * N + nn + 1] = v1;
                C[(size_t)(m + 8) * N + nn] = v2;
                C[(size_t)(m + 8) * N + nn + 1] = v3;
            }
        }
    }
}

// ---------------------------------------------------------------------------
// Assemble update-MLP input (bf16)
// ---------------------------------------------------------------------------
__global__ __launch_bounds__(128) void k_assemble() {
    int row = blockIdx.x;
    int n = row >> 4, t = row & 15;
    int tid = threadIdx.x;
    __shared__ float x4[4];
    if (tid == 0) {
        float cx = g_coords[(t * NQ + n) * 2 + 0];
        float cy = g_coords[(t * NQ + n) * 2 + 1];
        float rfx = 0.f, rfy = 0.f, rbx = 0.f, rby = 0.f;
        if (t < TT - 1) {
            rfx = (cx - g_coords[((t + 1) * NQ + n) * 2 + 0]) * (1.f / 128.f);
            rfy = (cy - g_coords[((t + 1) * NQ + n) * 2 + 1]) * (1.f / 96.f);
        }
        if (t > 0) {
            rbx = (cx - g_coords[((t - 1) * NQ + n) * 2 + 0]) * (1.f / 128.f);
            rby = (cy - g_coords[((t - 1) * NQ + n) * 2 + 1]) * (1.f / 96.f);
        }
        x4[0] = rfx; x4[1] = rfy; x4[2] = rbx; x4[3] = rby;
    }
    __syncthreads();
    __nv_bfloat16* dst = g_x + (size_t)row * X_K;
    for (int d = tid; d < D_IN; d += 128) {
        float v;
        if (d == 0) v = g_vis[t * NQ + n];
        else if (d == 1) v = g_conf[t * NQ + n];
        else if (d < 2 + 4 * EMB) {
            int qd = d - 2;
            int l = qd >> 8, k = qd & 255;
            v = g_e[(((size_t)(l * TT + t) * NQ + n) << 8) + k];
        } else {
            int j = d - (2 + 4 * EMB);
            if (j < 4) v = x4[j];
            else if (j < 44) {
                int s = (j - 4) >> 2, dd = (j - 4) & 3;
                v = sinf(x4[dd] * exp2f((float)s));
            } else {
                int s = (j - 44) >> 2, dd = (j - 44) & 3;
                v = cosf(x4[dd] * exp2f((float)s));
            }
        }
        dst[d] = __float2bfloat16(v + g_te[t * D_IN + d]);
    }
}

// ---------------------------------------------------------------------------
// Final tiny GEMV (384->4) + state update
// ---------------------------------------------------------------------------
__global__ __launch_bounds__(128) void k_update(const float* __restrict__ w2,
                                                const float* __restrict__ b2) {
    int row = blockIdx.x;
    int tid = threadIdx.x;
    const float* hrow = g_h2 + (size_t)row * HID;
    float a0 = 0.f, a1 = 0.f, a2 = 0.f, a3 = 0.f;
    for (int i = tid; i < HID; i += 128) {
        float h = hrow[i];
        const float* w = w2 + i * 4;
        a0 = fmaf(h, w[0], a0); a1 = fmaf(h, w[1], a1);
        a2 = fmaf(h, w[2], a2); a3 = fmaf(h, w[3], a3);
    }
#pragma unroll
    for (int o = 16; o; o >>= 1) {
        a0 += __shfl_xor_sync(0xffffffffu, a0, o);
        a1 += __shfl_xor_sync(0xffffffffu, a1, o);
        a2 += __shfl_xor_sync(0xffffffffu, a2, o);
        a3 += __shfl_xor_sync(0xffffffffu, a3, o);
    }
    __shared__ float red[4][4];
    int warp = tid >> 5, lane = tid & 31;
    if (lane == 0) { red[warp][0] = a0; red[warp][1] = a1; red[warp][2] = a2; red[warp][3] = a3; }
    __syncthreads();
    if (tid == 0) {
        float d0 = red[0][0] + red[1][0] + red[2][0] + red[3][0] + b2[0];
        float d1 = red[0][1] + red[1][1] + red[2][1] + red[3][1] + b2[1];
        float d2 = red[0][2] + red[1][2] + red[2][2] + red[3][2] + b2[2];
        float d3 = red[0][3] + red[1][3] + red[2][3] + red[3][3] + b2[3];
        int n = row >> 4, t = row & 15;
        g_coords[(t * NQ + n) * 2 + 0] += d0;
        g_coords[(t * NQ + n) * 2 + 1] += d1;
        g_vis[t * NQ + n]  += d2;
        g_conf[t * NQ + n] += d3;
    }
}

// ---------------------------------------------------------------------------
// Outputs
// ---------------------------------------------------------------------------
__global__ void k_output(float* __restrict__ out) {
    int i = blockIdx.x * blockDim.x + threadIdx.x;
    if (i >= 8192) return;
    if (i < 4096) out[i] = g_coords[i] * 4.f;
    else if (i < 6144) out[i] = 1.f / (1.f + expf(-g_vis[i - 4096]));
    else out[i] = 1.f / (1.f + expf(-g_conf[i - 6144]));
}

// ---------------------------------------------------------------------------
// Launch
// ---------------------------------------------------------------------------
extern "C" void kernel_launch(void* const* d_in, const int* in_sizes, int n_in,
                              void* d_out, int out_size) {
    const float* video   = (const float*)d_in[0];
    const float* queries = (const float*)d_in[1];
    const float* fnet_w  = (const float*)d_in[2];
    const float* fnet_b  = (const float*)d_in[3];
    const float* fc1_w   = (const float*)d_in[4];
    const float* fc1_b   = (const float*)d_in[5];
    const float* fc2_w   = (const float*)d_in[6];
    const float* fc2_b   = (const float*)d_in[7];
    const float* up_w1   = (const float*)d_in[8];
    const float* up_b1   = (const float*)d_in[9];
    const float* up_w2   = (const float*)d_in[10];
    const float* up_b2   = (const float*)d_in[11];
    const float* time_emb= (const float*)d_in[12];
    float* out = (float*)d_out;

    __nv_bfloat16 *p_cv, *p_h1, *p_x, *p_w1t, *p_w2t, *p_u1t;
    float *p_e, *p_h2;
    cudaGetSymbolAddress((void**)&p_cv,  g_cv);
    cudaGetSymbolAddress((void**)&p_h1,  g_h1);
    cudaGetSymbolAddress((void**)&p_e,   g_e);
    cudaGetSymbolAddress((void**)&p_x,   g_x);
    cudaGetSymbolAddress((void**)&p_h2,  g_h2);
    cudaGetSymbolAddress((void**)&p_w1t, g_w1t);
    cudaGetSymbolAddress((void**)&p_w2t, g_w2t);
    cudaGetSymbolAddress((void**)&p_u1t, g_u1t);

    const int M1 = 4 * TT * NQ;   // 8192
    const int M3 = NQ * TT;       // 2048

    // setup
    k_interp_te<<<(TT * D_IN + 255) / 256, 256>>>(time_emb);
    k_init<<<(TT * NQ + 127) / 128, 128>>>(queries);
    k_wt<<<(HID * CV_K + 255) / 256, 256>>>(fc1_w, p_w1t, 2401, HID, CV_K);
    k_wt<<<(EMB * HID + 255) / 256, 256>>>(fc2_w, p_w2t, HID, EMB, HID);
    k_wt<<<(HID * X_K + 255) / 256, 256>>>(up_w1, p_u1t, D_IN, HID, X_K);
    k_padzero<<<(M1 * (CV_K - 2401) + 255) / 256, 256>>>(p_cv, M1, CV_K, 2401, CV_K - 2401);
    k_padzero<<<(M3 * (X_K - D_IN) + 255) / 256, 256>>>(p_x, M3, X_K, D_IN, X_K - D_IN);
    k_conv<<<TT * 96 * 128 / 16, 128>>>(video, fnet_w, fnet_b);
    k_pool<<<(TT * 48 * 64 * LATC + 255) / 256, 256>>>(1);
    k_pool<<<(TT * 24 * 32 * LATC + 255) / 256, 256>>>(2);
    k_pool<<<(TT * 12 * 16 * LATC + 255) / 256, 256>>>(3);
    k_template<<<dim3(NQ, 4), 128>>>(queries);

    for (int it = 0; it < 4; it++) {
        k_corr_mma<<<dim3(NQ, TT, 4), 128>>>();
        k_gemm_bf<<<dim3(HID / 128, M1 / 128), 256>>>(p_cv, p_w1t, fc1_b, p_h1, M1, HID, CV_K, 1, 1);
        k_gemm_bf<<<dim3(EMB / 128, M1 / 128), 256>>>(p_h1, p_w2t, fc2_b, p_e, M1, EMB, HID, 0, 0);
        k_assemble<<<M3, 128>>>();
        k_gemm_bf<<<dim3(HID / 128, M3 / 128), 256>>>(p_x, p_u1t, up_b1, p_h2, M3, HID, X_K, 1, 0);
        k_update<<<M3, 128>>>(up_w2, up_b2);
    }
    k_output<<<(8192 + 255) / 256, 256>>>(out);
}